// round 4
// baseline (speedup 1.0000x reference)
#include <cuda_runtime.h>
#include <math.h>
#include <float.h>

#define MAXN 50000
#define MAXE 800000
#define MAXT (MAXE + MAXN)

// ---------------- scratch (device globals, referenced directly in kernels) ----------------
__device__ int   g_deg[MAXN];
__device__ int   g_off[MAXN + 1];
__device__ int   g_cur[MAXN];
__device__ int   g_srcs[MAXT];
__device__ __align__(16) float g_xl[MAXN * 128];
__device__ __align__(16) float g_xr[MAXN * 128];
__device__ __align__(16) float g_h [MAXN * 128];

// ---------------- CSR build ----------------
__global__ void zero_kernel(int n) {
    int i = blockIdx.x * blockDim.x + threadIdx.x;
    if (i < n) g_deg[i] = 0;
}

// edge_index is int32 (JAX x64 disabled: jnp.int64 silently becomes int32)
__global__ void hist_kernel(const int* __restrict__ ei, int E) {
    int e = blockIdx.x * blockDim.x + threadIdx.x;
    if (e < E) atomicAdd(&g_deg[ei[E + e]], 1);
}

// single-block exclusive scan over (deg[i]+1); writes off[0..n] and cur copy
__global__ void scan_kernel(int n) {
    __shared__ int sh[1024];
    int t  = threadIdx.x;
    int cs = (n + 1023) >> 10;
    int b  = t * cs;
    int e  = b + cs; if (e > n) e = n; if (e < b) e = b;
    int s = 0;
    for (int i = b; i < e; ++i) s += g_deg[i] + 1;
    sh[t] = s;
    __syncthreads();
    for (int o = 1; o < 1024; o <<= 1) {
        int add = (t >= o) ? sh[t - o] : 0;
        __syncthreads();
        sh[t] += add;
        __syncthreads();
    }
    int run = sh[t] - s;  // exclusive prefix
    for (int i = b; i < e; ++i) {
        g_off[i] = run; g_cur[i] = run;
        run += g_deg[i] + 1;
    }
    if (t == 1023) g_off[n] = run;
}

__global__ void scatter_kernel(const int* __restrict__ ei, int E, int n) {
    int i = blockIdx.x * blockDim.x + threadIdx.x;
    if (i < E) {
        int d = ei[E + i];
        int p = atomicAdd(&g_cur[d], 1);
        g_srcs[p] = ei[i];
    } else if (i < E + n) {
        int v = i - E;               // self loop
        int p = atomicAdd(&g_cur[v], 1);
        g_srcs[p] = v;
    }
}

// ---------------- SGEMM: C[n,M] = A[n,K] @ W[K,M] ----------------
// a_ext: A = Aext if true, else g_h.  c_sel: 0 -> g_xl, 1 -> g_xr, 2 -> Cext.
// BM=128, BK=8, 256 threads, micro-tile 8 x TN. BN in {128,64}, TN = BN/16.
template <int BN, int TN>
__global__ __launch_bounds__(256) void sgemm(const float* __restrict__ Aext, int a_ext,
                                             const float* __restrict__ W,
                                             int c_sel, float* __restrict__ Cext,
                                             int n, int K, int M) {
    const float* A = a_ext ? Aext : g_h;
    float* C = (c_sel == 0) ? g_xl : (c_sel == 1) ? g_xr : Cext;

    __shared__ float As[8][128];
    __shared__ float Bs[8][BN];
    int t  = threadIdx.x;
    int tx = t & 15;       // column group
    int ty = t >> 4;       // row group
    int row0 = blockIdx.y * 128;
    int col0 = blockIdx.x * BN;

    float acc[8][TN];
    #pragma unroll
    for (int i = 0; i < 8; ++i)
        #pragma unroll
        for (int j = 0; j < TN; ++j) acc[i][j] = 0.f;

    for (int k0 = 0; k0 < K; k0 += 8) {
        // A tile: 128x8 = 1024 floats, 4/thread (float4 along K)
        {
            int i = t * 4;
            int r = i >> 3;
            int c = i & 7;
            int gr = row0 + r;
            float4 v = make_float4(0.f, 0.f, 0.f, 0.f);
            if (gr < n) v = *reinterpret_cast<const float4*>(A + (size_t)gr * K + k0 + c);
            As[c + 0][r] = v.x; As[c + 1][r] = v.y; As[c + 2][r] = v.z; As[c + 3][r] = v.w;
        }
        // W tile: 8xBN
        {
            constexpr int BL = (8 * BN) / 256;   // 4 or 2
            int i  = t * BL;
            int br = i / BN;
            int bc = i % BN;
            if (BL == 4) {
                *reinterpret_cast<float4*>(&Bs[br][bc]) =
                    *reinterpret_cast<const float4*>(W + (size_t)(k0 + br) * M + col0 + bc);
            } else {
                *reinterpret_cast<float2*>(&Bs[br][bc]) =
                    *reinterpret_cast<const float2*>(W + (size_t)(k0 + br) * M + col0 + bc);
            }
        }
        __syncthreads();
        #pragma unroll
        for (int kk = 0; kk < 8; ++kk) {
            float a[8], b[TN];
            #pragma unroll
            for (int i = 0; i < 8; ++i) a[i] = As[kk][ty * 8 + i];
            #pragma unroll
            for (int j = 0; j < TN; ++j) b[j] = Bs[kk][tx * TN + j];
            #pragma unroll
            for (int i = 0; i < 8; ++i)
                #pragma unroll
                for (int j = 0; j < TN; ++j) acc[i][j] = fmaf(a[i], b[j], acc[i][j]);
        }
        __syncthreads();
    }
    #pragma unroll
    for (int i = 0; i < 8; ++i) {
        int gr = row0 + ty * 8 + i;
        if (gr < n) {
            #pragma unroll
            for (int j = 0; j < TN; j += 4) {
                float4 v = make_float4(acc[i][j], acc[i][j + 1], acc[i][j + 2], acc[i][j + 3]);
                *reinterpret_cast<float4*>(C + (size_t)gr * M + col0 + tx * TN + j) = v;
            }
        }
    }
}

// ---------------- fused attention + online softmax + aggregate ----------------
// one warp per dst node; F = H*C total channels; lane holds channels [lane*VPL, ...)
// reads g_xl/g_xr; out_ext ? Cext : g_h
template <int F, int C, bool DOELU>
__global__ __launch_bounds__(256) void edge_kernel(
    const float* __restrict__ att, const float* __restrict__ bias,
    int out_ext, float* __restrict__ Cext, int n) {
    constexpr int VPL = F / 32;       // values per lane (4 or 2)
    constexpr int GR  = C / VPL;      // lanes per head group (8 or 32)
    float* out = out_ext ? Cext : g_h;
    int w    = (blockIdx.x * blockDim.x + threadIdx.x) >> 5;
    int lane = threadIdx.x & 31;
    if (w >= n) return;

    float xrv[VPL], av[VPL], bv[VPL];
    if (VPL == 4) {
        float4 t0 = *reinterpret_cast<const float4*>(g_xr + (size_t)w * F + lane * 4);
        xrv[0] = t0.x; xrv[1] = t0.y; xrv[2] = t0.z; xrv[3] = t0.w;
        float4 t1 = *reinterpret_cast<const float4*>(att + lane * 4);
        av[0] = t1.x; av[1] = t1.y; av[2] = t1.z; av[3] = t1.w;
        float4 t2 = *reinterpret_cast<const float4*>(bias + lane * 4);
        bv[0] = t2.x; bv[1] = t2.y; bv[2] = t2.z; bv[3] = t2.w;
    } else {
        float2 t0 = *reinterpret_cast<const float2*>(g_xr + (size_t)w * F + lane * 2);
        xrv[0] = t0.x; xrv[1] = t0.y;
        float2 t1 = *reinterpret_cast<const float2*>(att + lane * 2);
        av[0] = t1.x; av[1] = t1.y;
        float2 t2 = *reinterpret_cast<const float2*>(bias + lane * 2);
        bv[0] = t2.x; bv[1] = t2.y;
    }

    float mh = -INFINITY, ssum = 0.f;
    float acc[VPL];
    #pragma unroll
    for (int j = 0; j < VPL; ++j) acc[j] = 0.f;

    int e0 = g_off[w], e1 = g_off[w + 1];
    for (int e = e0; e < e1; ++e) {
        int s = g_srcs[e];
        float xv[VPL];
        if (VPL == 4) {
            float4 t = *reinterpret_cast<const float4*>(g_xl + (size_t)s * F + lane * 4);
            xv[0] = t.x; xv[1] = t.y; xv[2] = t.z; xv[3] = t.w;
        } else {
            float2 t = *reinterpret_cast<const float2*>(g_xl + (size_t)s * F + lane * 2);
            xv[0] = t.x; xv[1] = t.y;
        }
        float p = 0.f;
        #pragma unroll
        for (int j = 0; j < VPL; ++j) {
            float m  = xv[j] + xrv[j];
            float lr = (m > 0.f) ? m : 0.2f * m;      // leaky_relu(0.2)
            p = fmaf(av[j], lr, p);
        }
        #pragma unroll
        for (int o = 1; o < GR; o <<= 1) p += __shfl_xor_sync(0xffffffffu, p, o);
        // online softmax update (per head; state replicated within head group)
        float nm    = fmaxf(mh, p);
        float scale = __expf(mh - nm);
        float wgt   = __expf(p - nm);
        ssum = ssum * scale + wgt;
        #pragma unroll
        for (int j = 0; j < VPL; ++j) acc[j] = fmaf(acc[j], scale, wgt * xv[j]);
        mh = nm;
    }
    float inv = 1.f / ssum;
    float o_[VPL];
    #pragma unroll
    for (int j = 0; j < VPL; ++j) {
        float v = fmaf(acc[j], inv, bv[j]);
        if (DOELU) v = (v > 0.f) ? v : expm1f(v);
        o_[j] = v;
    }
    if (VPL == 4) {
        *reinterpret_cast<float4*>(out + (size_t)w * F + lane * 4) =
            make_float4(o_[0], o_[1], o_[2], o_[3]);
    } else {
        *reinterpret_cast<float2*>(out + (size_t)w * F + lane * 2) =
            make_float2(o_[0], o_[1]);
    }
}

// ---------------- launch (kernel launches ONLY) ----------------
extern "C" void kernel_launch(void* const* d_in, const int* in_sizes, int n_in,
                              void* d_out, int out_size) {
    const float* x   = (const float*)d_in[0];
    const int*   ei  = (const int*)d_in[1];     // int32 edge_index
    const float* Wl1 = (const float*)d_in[2];
    const float* Wr1 = (const float*)d_in[3];
    const float* a1  = (const float*)d_in[4];
    const float* b1  = (const float*)d_in[5];
    const float* Wl2 = (const float*)d_in[6];
    const float* Wr2 = (const float*)d_in[7];
    const float* a2  = (const float*)d_in[8];
    const float* b2  = (const float*)d_in[9];
    const float* Wl3 = (const float*)d_in[10];
    const float* Wr3 = (const float*)d_in[11];
    const float* a3  = (const float*)d_in[12];
    const float* b3  = (const float*)d_in[13];
    float* out = (float*)d_out;

    int N = in_sizes[0] / 128;
    int E = in_sizes[1] / 2;

    // CSR-by-dst (built once, shared by all layers)
    zero_kernel<<<(N + 255) / 256, 256>>>(N);
    hist_kernel<<<(E + 255) / 256, 256>>>(ei, E);
    scan_kernel<<<1, 1024>>>(N);
    scatter_kernel<<<(E + N + 255) / 256, 256>>>(ei, E, N);

    dim3 gFull(1, (N + 127) / 128);   // M=128, BN=128
    dim3 gHalf(1, (N + 127) / 128);   // M=64,  BN=64
    int  eBlocks = (N + 7) / 8;       // 8 warps / block

    // layer 1: 128 -> 4x32, concat + ELU   (A = x external, C -> g_xl/g_xr)
    sgemm<128, 8><<<gFull, 256>>>(x, 1, Wl1, 0, nullptr, N, 128, 128);
    sgemm<128, 8><<<gFull, 256>>>(x, 1, Wr1, 1, nullptr, N, 128, 128);
    edge_kernel<128, 32, true><<<eBlocks, 256>>>(a1, b1, 0, nullptr, N);

    // layer 2 (A = g_h internal)
    sgemm<128, 8><<<gFull, 256>>>(nullptr, 0, Wl2, 0, nullptr, N, 128, 128);
    sgemm<128, 8><<<gFull, 256>>>(nullptr, 0, Wr2, 1, nullptr, N, 128, 128);
    edge_kernel<128, 32, true><<<eBlocks, 256>>>(a2, b2, 0, nullptr, N);

    // layer 3: 128 -> 64, heads=1, no ELU, write d_out
    sgemm<64, 4><<<gHalf, 256>>>(nullptr, 0, Wl3, 0, nullptr, N, 128, 64);
    sgemm<64, 4><<<gHalf, 256>>>(nullptr, 0, Wr3, 1, nullptr, N, 128, 64);
    edge_kernel<64, 64, false><<<eBlocks, 256>>>(a3, b3, 1, out, N);
}

// round 5
// speedup vs baseline: 1.0866x; 1.0866x over previous
#include <cuda_runtime.h>
#include <math.h>
#include <float.h>

#define MAXN 50000
#define MAXE 800000
#define MAXT (MAXE + MAXN)

// ---------------- scratch (device globals, referenced directly in kernels) ----------------
__device__ int   g_deg[MAXN];
__device__ int   g_off[MAXN + 1];
__device__ int   g_cur[MAXN];
__device__ int   g_srcs[MAXT];
__device__ __align__(16) float g_xl[MAXN * 128];
__device__ __align__(16) float g_xr[MAXN * 128];
__device__ __align__(16) float g_h [MAXN * 128];

// ---------------- packed f32x2 helpers (sm_103a FFMA2 path) ----------------
#define FMA_F32X2(d, a, b, c) \
    asm("fma.rn.f32x2 %0, %1, %2, %3;" : "=l"(d) : "l"(a), "l"(b), "l"(c))
#define PACK_F32X2(out, lo, hi) \
    asm("mov.b64 %0, {%1, %2};" : "=l"(out) : "f"(lo), "f"(hi))
#define UNPACK_F32X2(lo, hi, in) \
    asm("mov.b64 {%0, %1}, %2;" : "=f"(lo), "=f"(hi) : "l"(in))

// ---------------- CSR build ----------------
__global__ void zero_kernel(int n) {
    int i = blockIdx.x * blockDim.x + threadIdx.x;
    if (i < n) g_deg[i] = 0;
}

// edge_index is int32 (JAX x64 disabled: jnp.int64 silently becomes int32)
__global__ void hist_kernel(const int* __restrict__ ei, int E) {
    int e = blockIdx.x * blockDim.x + threadIdx.x;
    if (e < E) atomicAdd(&g_deg[ei[E + e]], 1);
}

// single-block exclusive scan over (deg[i]+1); writes off[0..n] and cur copy
__global__ void scan_kernel(int n) {
    __shared__ int sh[1024];
    int t  = threadIdx.x;
    int cs = (n + 1023) >> 10;
    int b  = t * cs;
    int e  = b + cs; if (e > n) e = n; if (e < b) e = b;
    int s = 0;
    for (int i = b; i < e; ++i) s += g_deg[i] + 1;
    sh[t] = s;
    __syncthreads();
    for (int o = 1; o < 1024; o <<= 1) {
        int add = (t >= o) ? sh[t - o] : 0;
        __syncthreads();
        sh[t] += add;
        __syncthreads();
    }
    int run = sh[t] - s;  // exclusive prefix
    for (int i = b; i < e; ++i) {
        g_off[i] = run; g_cur[i] = run;
        run += g_deg[i] + 1;
    }
    if (t == 1023) g_off[n] = run;
}

__global__ void scatter_kernel(const int* __restrict__ ei, int E, int n) {
    int i = blockIdx.x * blockDim.x + threadIdx.x;
    if (i < E) {
        int d = ei[E + i];
        int p = atomicAdd(&g_cur[d], 1);
        g_srcs[p] = ei[i];
    } else if (i < E + n) {
        int v = i - E;               // self loop
        int p = atomicAdd(&g_cur[v], 1);
        g_srcs[p] = v;
    }
}

// ---------------- SGEMM (f32x2 packed): C[n,M] = A[n,K] @ W[K,M] ----------------
// BM=128, BK=16, 256 threads. BN in {128,64}, TN = BN/16 per-thread columns.
// Accumulators pair adjacent M rows in one 64-bit f32x2 register.
// a_ext: A = Aext if true, else g_h.  c_sel: 0 -> g_xl, 1 -> g_xr, 2 -> Cext.
template <int BN, int TN>
__global__ __launch_bounds__(256, 2) void sgemm2(const float* __restrict__ Aext, int a_ext,
                                                 const float* __restrict__ W,
                                                 int c_sel, float* __restrict__ Cext,
                                                 int n, int K, int M) {
    const float* A = a_ext ? Aext : g_h;
    float* C = (c_sel == 0) ? g_xl : (c_sel == 1) ? g_xr : Cext;

    __shared__ float As[16][132];     // padded stride kills STS bank conflicts
    __shared__ float Bs[16][BN];
    int t  = threadIdx.x;
    int tx = t & 15;                  // column group (16)
    int ty = t >> 4;                  // row group (16) -> rows ty*8 .. ty*8+7
    int row0 = blockIdx.y * 128;
    int col0 = blockIdx.x * BN;

    unsigned long long acc[4][TN];    // 4 m-pairs x TN cols, f32x2 each; 0ull == {0,0}
    #pragma unroll
    for (int i = 0; i < 4; ++i)
        #pragma unroll
        for (int j = 0; j < TN; ++j) acc[i][j] = 0ull;

    for (int k0 = 0; k0 < K; k0 += 16) {
        // ---- A tile: 128 rows x 16 k. 2 float4 per thread ----
        {
            int q  = t & 3;           // k-quad
            int r2 = t >> 2;          // 0..63
            #pragma unroll
            for (int p = 0; p < 2; ++p) {
                int r  = r2 + p * 64;
                int gr = row0 + r;
                float4 v = make_float4(0.f, 0.f, 0.f, 0.f);
                if (gr < n) v = *reinterpret_cast<const float4*>(A + (size_t)gr * K + k0 + q * 4);
                As[q * 4 + 0][r] = v.x; As[q * 4 + 1][r] = v.y;
                As[q * 4 + 2][r] = v.z; As[q * 4 + 3][r] = v.w;
            }
        }
        // ---- W tile: 16 x BN, direct float4 ----
        {
            constexpr int QPR    = BN / 4;       // float4s per row
            constexpr int RPP    = 256 / QPR;    // k-rows per pass
            constexpr int PASSES = 16 / RPP;
            int kr = t / QPR;
            int cq = t % QPR;
            #pragma unroll
            for (int p = 0; p < PASSES; ++p) {
                *reinterpret_cast<float4*>(&Bs[kr + p * RPP][cq * 4]) =
                    *reinterpret_cast<const float4*>(W + (size_t)(k0 + kr + p * RPP) * M + col0 + cq * 4);
            }
        }
        __syncthreads();
        #pragma unroll
        for (int kk = 0; kk < 16; ++kk) {
            unsigned long long a2[4];
            #pragma unroll
            for (int i = 0; i < 4; ++i)
                a2[i] = *reinterpret_cast<const unsigned long long*>(&As[kk][ty * 8 + 2 * i]);
            unsigned long long b2[TN];
            #pragma unroll
            for (int j4 = 0; j4 < TN; j4 += 4) {
                float4 bq = *reinterpret_cast<const float4*>(&Bs[kk][tx * TN + j4]);
                PACK_F32X2(b2[j4 + 0], bq.x, bq.x);
                PACK_F32X2(b2[j4 + 1], bq.y, bq.y);
                PACK_F32X2(b2[j4 + 2], bq.z, bq.z);
                PACK_F32X2(b2[j4 + 3], bq.w, bq.w);
            }
            #pragma unroll
            for (int i = 0; i < 4; ++i)
                #pragma unroll
                for (int j = 0; j < TN; ++j)
                    FMA_F32X2(acc[i][j], a2[i], b2[j], acc[i][j]);
        }
        __syncthreads();
    }
    // ---- epilogue: unpack pairs, store per-row float4s ----
    #pragma unroll
    for (int i = 0; i < 4; ++i) {
        int gr = row0 + ty * 8 + 2 * i;
        float lo[TN], hi[TN];
        #pragma unroll
        for (int j = 0; j < TN; ++j) UNPACK_F32X2(lo[j], hi[j], acc[i][j]);
        if (gr < n) {
            #pragma unroll
            for (int j = 0; j < TN; j += 4)
                *reinterpret_cast<float4*>(C + (size_t)gr * M + col0 + tx * TN + j) =
                    make_float4(lo[j], lo[j + 1], lo[j + 2], lo[j + 3]);
        }
        if (gr + 1 < n) {
            #pragma unroll
            for (int j = 0; j < TN; j += 4)
                *reinterpret_cast<float4*>(C + (size_t)(gr + 1) * M + col0 + tx * TN + j) =
                    make_float4(hi[j], hi[j + 1], hi[j + 2], hi[j + 3]);
        }
    }
}

// ---------------- fused attention + online softmax + aggregate ----------------
// one warp per dst node; F = H*C total channels; lane holds channels [lane*VPL, ...)
// reads g_xl/g_xr; out_ext ? Cext : g_h
template <int F, int C, bool DOELU>
__global__ __launch_bounds__(256) void edge_kernel(
    const float* __restrict__ att, const float* __restrict__ bias,
    int out_ext, float* __restrict__ Cext, int n) {
    constexpr int VPL = F / 32;       // values per lane (4 or 2)
    constexpr int GR  = C / VPL;      // lanes per head group (8 or 32)
    float* out = out_ext ? Cext : g_h;
    int w    = (blockIdx.x * blockDim.x + threadIdx.x) >> 5;
    int lane = threadIdx.x & 31;
    if (w >= n) return;

    float xrv[VPL], av[VPL], bv[VPL];
    if (VPL == 4) {
        float4 t0 = *reinterpret_cast<const float4*>(g_xr + (size_t)w * F + lane * 4);
        xrv[0] = t0.x; xrv[1] = t0.y; xrv[2] = t0.z; xrv[3] = t0.w;
        float4 t1 = *reinterpret_cast<const float4*>(att + lane * 4);
        av[0] = t1.x; av[1] = t1.y; av[2] = t1.z; av[3] = t1.w;
        float4 t2 = *reinterpret_cast<const float4*>(bias + lane * 4);
        bv[0] = t2.x; bv[1] = t2.y; bv[2] = t2.z; bv[3] = t2.w;
    } else {
        float2 t0 = *reinterpret_cast<const float2*>(g_xr + (size_t)w * F + lane * 2);
        xrv[0] = t0.x; xrv[1] = t0.y;
        float2 t1 = *reinterpret_cast<const float2*>(att + lane * 2);
        av[0] = t1.x; av[1] = t1.y;
        float2 t2 = *reinterpret_cast<const float2*>(bias + lane * 2);
        bv[0] = t2.x; bv[1] = t2.y;
    }

    float mh = -INFINITY, ssum = 0.f;
    float acc[VPL];
    #pragma unroll
    for (int j = 0; j < VPL; ++j) acc[j] = 0.f;

    int e0 = g_off[w], e1 = g_off[w + 1];
    for (int e = e0; e < e1; ++e) {
        int s = g_srcs[e];
        float xv[VPL];
        if (VPL == 4) {
            float4 t = *reinterpret_cast<const float4*>(g_xl + (size_t)s * F + lane * 4);
            xv[0] = t.x; xv[1] = t.y; xv[2] = t.z; xv[3] = t.w;
        } else {
            float2 t = *reinterpret_cast<const float2*>(g_xl + (size_t)s * F + lane * 2);
            xv[0] = t.x; xv[1] = t.y;
        }
        float p = 0.f;
        #pragma unroll
        for (int j = 0; j < VPL; ++j) {
            float m  = xv[j] + xrv[j];
            float lr = (m > 0.f) ? m : 0.2f * m;      // leaky_relu(0.2)
            p = fmaf(av[j], lr, p);
        }
        #pragma unroll
        for (int o = 1; o < GR; o <<= 1) p += __shfl_xor_sync(0xffffffffu, p, o);
        // online softmax update (per head; state replicated within head group)
        float nm    = fmaxf(mh, p);
        float scale = __expf(mh - nm);
        float wgt   = __expf(p - nm);
        ssum = ssum * scale + wgt;
        #pragma unroll
        for (int j = 0; j < VPL; ++j) acc[j] = fmaf(acc[j], scale, wgt * xv[j]);
        mh = nm;
    }
    float inv = 1.f / ssum;
    float o_[VPL];
    #pragma unroll
    for (int j = 0; j < VPL; ++j) {
        float v = fmaf(acc[j], inv, bv[j]);
        if (DOELU) v = (v > 0.f) ? v : expm1f(v);
        o_[j] = v;
    }
    if (VPL == 4) {
        *reinterpret_cast<float4*>(out + (size_t)w * F + lane * 4) =
            make_float4(o_[0], o_[1], o_[2], o_[3]);
    } else {
        *reinterpret_cast<float2*>(out + (size_t)w * F + lane * 2) =
            make_float2(o_[0], o_[1]);
    }
}

// ---------------- launch (kernel launches ONLY) ----------------
extern "C" void kernel_launch(void* const* d_in, const int* in_sizes, int n_in,
                              void* d_out, int out_size) {
    const float* x   = (const float*)d_in[0];
    const int*   ei  = (const int*)d_in[1];     // int32 edge_index
    const float* Wl1 = (const float*)d_in[2];
    const float* Wr1 = (const float*)d_in[3];
    const float* a1  = (const float*)d_in[4];
    const float* b1  = (const float*)d_in[5];
    const float* Wl2 = (const float*)d_in[6];
    const float* Wr2 = (const float*)d_in[7];
    const float* a2  = (const float*)d_in[8];
    const float* b2  = (const float*)d_in[9];
    const float* Wl3 = (const float*)d_in[10];
    const float* Wr3 = (const float*)d_in[11];
    const float* a3  = (const float*)d_in[12];
    const float* b3  = (const float*)d_in[13];
    float* out = (float*)d_out;

    int N = in_sizes[0] / 128;
    int E = in_sizes[1] / 2;

    // CSR-by-dst (built once, shared by all layers)
    zero_kernel<<<(N + 255) / 256, 256>>>(N);
    hist_kernel<<<(E + 255) / 256, 256>>>(ei, E);
    scan_kernel<<<1, 1024>>>(N);
    scatter_kernel<<<(E + N + 255) / 256, 256>>>(ei, E, N);

    dim3 gFull(1, (N + 127) / 128);   // M=128, BN=128
    dim3 gHalf(1, (N + 127) / 128);   // M=64,  BN=64
    int  eBlocks = (N + 7) / 8;       // 8 warps / block

    // layer 1: 128 -> 4x32, concat + ELU   (A = x external, C -> g_xl/g_xr)
    sgemm2<128, 8><<<gFull, 256>>>(x, 1, Wl1, 0, nullptr, N, 128, 128);
    sgemm2<128, 8><<<gFull, 256>>>(x, 1, Wr1, 1, nullptr, N, 128, 128);
    edge_kernel<128, 32, true><<<eBlocks, 256>>>(a1, b1, 0, nullptr, N);

    // layer 2 (A = g_h internal)
    sgemm2<128, 8><<<gFull, 256>>>(nullptr, 0, Wl2, 0, nullptr, N, 128, 128);
    sgemm2<128, 8><<<gFull, 256>>>(nullptr, 0, Wr2, 1, nullptr, N, 128, 128);
    edge_kernel<128, 32, true><<<eBlocks, 256>>>(a2, b2, 0, nullptr, N);

    // layer 3: 128 -> 64, heads=1, no ELU, write d_out
    sgemm2<64, 4><<<gHalf, 256>>>(nullptr, 0, Wl3, 0, nullptr, N, 128, 64);
    sgemm2<64, 4><<<gHalf, 256>>>(nullptr, 0, Wr3, 1, nullptr, N, 128, 64);
    edge_kernel<64, 64, false><<<eBlocks, 256>>>(a3, b3, 1, out, N);
}